// round 15
// baseline (speedup 1.0000x reference)
#include <cuda_runtime.h>
#include <cuda_fp16.h>
#include <cstdint>

// ===================== problem constants =====================
#define M_TOTAL 8192
#define N_TOTAL 4096
#define K_TOTAL 4096
#define THRESH  0.1f

// ===================== GEMM tiling =====================
// One 384-thread CTA = THREE independent 4-warp pipelines ("groups").
// Each group: 128x64 output tile, THREE-stage ring, own named barrier.
// Warp tile 64x32. wait_group 1 keeps one stage in flight across the wait.
// Loop body ordered: barrier -> ks0 LDSM -> cp.async prefetch -> MMAs,
// so the prefetch issue burst rides in the LDSM/MMA shadow.
#define BM 128
#define BN 64
#define BK 64            // halves per k-stage (128 bytes per row)
#define STAGES 3
#define GROUPS 3
#define GTHREADS 384
#define NKT (K_TOTAL / BK)                          // 64
#define NT  (N_TOTAL / BN)                          // 64 n-tiles
#define NTILES ((M_TOTAL / BM) * NT)                // 4096

#define A_REGION     (BM * BK * 2)                  // 16384
#define STAGE_BYTES  ((BM + BN) * BK * 2)           // 24576
#define GROUP_BYTES  (STAGES * STAGE_BYTES)         // 73728
#define SMEM_BYTES   (GROUPS * GROUP_BYTES)         // 221184 (<= 227KB cap)

// ===================== scratch (device globals, allocation-free) ==========
__device__ __half g_A[(size_t)M_TOTAL * K_TOTAL];   // 64 MB, x in fp16
__device__ __half g_B[(size_t)N_TOTAL * K_TOTAL];   // 32 MB, ternary(w) in fp16

// ===================== helpers =====================
static __device__ __forceinline__ uint32_t smem_u32(const void* p) {
    uint32_t a;
    asm("{ .reg .u64 t; cvta.to.shared.u64 t, %1; cvt.u32.u64 %0, t; }"
        : "=r"(a) : "l"(p));
    return a;
}

static __device__ __forceinline__ void cp16(uint32_t dst, const void* src) {
    asm volatile("cp.async.cg.shared.global [%0], [%1], 16;"
                 :: "r"(dst), "l"(src) : "memory");
}
#define CP_COMMIT() asm volatile("cp.async.commit_group;" ::: "memory")
#define CP_WAIT1()  asm volatile("cp.async.wait_group 1;"  ::: "memory")

// named barrier: independent sync domain per 4-warp group (128 threads)
static __device__ __forceinline__ void barg(int id) {
    asm volatile("bar.sync %0, %1;" :: "r"(id), "r"(128) : "memory");
}

static __device__ __forceinline__ void ldm_x4(uint32_t* r, uint32_t addr) {
    asm volatile("ldmatrix.sync.aligned.m8n8.x4.shared.b16 {%0,%1,%2,%3}, [%4];"
                 : "=r"(r[0]), "=r"(r[1]), "=r"(r[2]), "=r"(r[3]) : "r"(addr));
}

static __device__ __forceinline__ void mma16816(float* c, const uint32_t* a,
                                                uint32_t b0, uint32_t b1) {
    asm volatile(
        "mma.sync.aligned.m16n8k16.row.col.f32.f16.f16.f32 "
        "{%0,%1,%2,%3}, {%4,%5,%6,%7}, {%8,%9}, {%0,%1,%2,%3};"
        : "+f"(c[0]), "+f"(c[1]), "+f"(c[2]), "+f"(c[3])
        : "r"(a[0]), "r"(a[1]), "r"(a[2]), "r"(a[3]), "r"(b0), "r"(b1));
}

static __device__ __forceinline__ void stcs2(float* p, float x, float y) {
    asm volatile("st.global.cs.v2.f32 [%0], {%1, %2};" :: "l"(p), "f"(x), "f"(y) : "memory");
}

// ===================== merged pack kernel =====================
static __device__ __forceinline__ float tern(float v) {
    return (v > THRESH) ? 1.0f : ((v < -THRESH) ? -1.0f : 0.0f);
}

#define TX_CHUNKS ((size_t)M_TOTAL * K_TOTAL / 8)   // 4,194,304
#define TW_CHUNKS ((size_t)N_TOTAL * K_TOTAL / 8)   // 2,097,152

__global__ void __launch_bounds__(512) pack_both_kernel(const float4* __restrict__ x,
                                                        const float4* __restrict__ w) {
    size_t i = (size_t)blockIdx.x * blockDim.x + threadIdx.x;
    if (i < TX_CHUNKS) {
        float4 v0 = __ldcs(&x[i * 2]);       // streaming: keep L2 for g_A/g_B
        float4 v1 = __ldcs(&x[i * 2 + 1]);
        __half2 h0 = __floats2half2_rn(v0.x, v0.y);
        __half2 h1 = __floats2half2_rn(v0.z, v0.w);
        __half2 h2 = __floats2half2_rn(v1.x, v1.y);
        __half2 h3 = __floats2half2_rn(v1.z, v1.w);
        uint4 u;
        u.x = *(uint32_t*)&h0; u.y = *(uint32_t*)&h1;
        u.z = *(uint32_t*)&h2; u.w = *(uint32_t*)&h3;
        *(uint4*)(&g_A[i * 8]) = u;
    } else {
        size_t j = i - TX_CHUNKS;
        if (j >= TW_CHUNKS) return;
        float4 v0 = __ldcs(&w[j * 2]);
        float4 v1 = __ldcs(&w[j * 2 + 1]);
        __half2 h0 = __floats2half2_rn(tern(v0.x), tern(v0.y));
        __half2 h1 = __floats2half2_rn(tern(v0.z), tern(v0.w));
        __half2 h2 = __floats2half2_rn(tern(v1.x), tern(v1.y));
        __half2 h3 = __floats2half2_rn(tern(v1.z), tern(v1.w));
        uint4 u;
        u.x = *(uint32_t*)&h0; u.y = *(uint32_t*)&h1;
        u.z = *(uint32_t*)&h2; u.w = *(uint32_t*)&h3;
        *(uint4*)(&g_B[j * 8]) = u;
    }
}

// ===================== GEMM kernel =====================
// A fp16 [M][K] row-major, B fp16 [N][K] row-major (TN gemm).
// SMEM rows 128B; swizzle: 16B-chunk c -> c ^ (row & 7).
// Group g handles tile (blockIdx.x*3 + g); 3-stage ring:
//   kt: wait_group 1 -> barg -> ks0 LDSM -> issue kt+2 -> ks0 MMA -> ks1..3.
__global__ void __launch_bounds__(GTHREADS, 1)
gemm_kernel(float* __restrict__ out, const float* __restrict__ bias) {
    extern __shared__ __half smem[];
    const uint32_t sbase = smem_u32(smem);

    const int tid   = threadIdx.x;
    const int g     = tid >> 7;          // group 0..2
    const int lane  = tid & 31;
    const int wid_g = (tid >> 5) & 3;    // warp within group
    const int wm    = wid_g & 1;         // 0..1 : M (64-row slab)
    const int wn    = wid_g >> 1;        // 0..1 : N (32-col slab)
    const int barid = g + 1;

    const int t  = blockIdx.x * GROUPS + g;   // this group's tile
    if (t >= NTILES) return;                  // safe: barriers are group-local
    const int m0 = (t >> 6) * BM;             // NT = 64 n-tiles
    const int n0 = (t & 63) * BN;

    const __half* gA = g_A + (size_t)m0 * K_TOTAL;
    const __half* gB = g_B + (size_t)n0 * K_TOTAL;

    const uint32_t gbase = sbase + g * GROUP_BYTES;

    const int tg    = tid & 127;
    const int ldrow = tg >> 3;           // 0..15
    const int ldcol = tg & 7;            // 16B chunk 0..7
    const uint32_t ldsw = (uint32_t)((ldcol ^ (ldrow & 7)) << 4);

    // ---- async stage loader: A 128 rows + B 64 rows, 128B each, 128 thr ----
    auto issue_stage = [&](int kt, int s) {
        const uint32_t stA = gbase + s * STAGE_BYTES;
        const uint32_t stB = stA + A_REGION;
        const int kofs = kt * BK + ldcol * 8;
        #pragma unroll
        for (int i = 0; i < 8; ++i) {
            const int row = ldrow + i * 16;
            cp16(stA + row * 128 + ldsw, gA + (size_t)row * K_TOTAL + kofs);
        }
        #pragma unroll
        for (int i = 0; i < 4; ++i) {
            const int row = ldrow + i * 16;
            cp16(stB + row * 128 + ldsw, gB + (size_t)row * K_TOTAL + kofs);
        }
    };

    // fragment loads for one ks step
    auto load_frags = [&](uint32_t stA, uint32_t stB, int ks,
                          uint32_t afr[4][4], uint32_t bfr[2][4]) {
        const int chunk = 2 * ks + (lane >> 4);
        #pragma unroll
        for (int mf = 0; mf < 4; ++mf) {
            const int row = wm * 64 + mf * 16 + (lane & 15);
            ldm_x4(afr[mf], stA + row * 128 + ((chunk ^ (row & 7)) << 4));
        }
        #pragma unroll
        for (int nh = 0; nh < 2; ++nh) {
            const int row = wn * 32 + nh * 16 + (lane & 15);
            ldm_x4(bfr[nh], stB + row * 128 + ((chunk ^ (row & 7)) << 4));
        }
    };

    // prologue: stages 0,1
    issue_stage(0, 0); CP_COMMIT();
    issue_stage(1, 1); CP_COMMIT();

    float acc[4][4][4];
    #pragma unroll
    for (int i = 0; i < 4; ++i)
        #pragma unroll
        for (int j = 0; j < 4; ++j)
            #pragma unroll
            for (int e = 0; e < 4; ++e) acc[i][j][e] = 0.0f;

    int s = 0;                            // ring slot of kt
    #pragma unroll 1
    for (int kt = 0; kt < NKT; ++kt) {
        CP_WAIT1();                       // slot kt landed; kt+1 may still fly
        barg(barid);                      // group-wide publish + reuse safety

        const uint32_t stA = gbase + s * STAGE_BYTES;
        const uint32_t stB = stA + A_REGION;

        // ks=0 critical loads FIRST
        uint32_t afr[4][4], bfr[2][4];
        load_frags(stA, stB, 0, afr, bfr);

        // prefetch kt+2 in the LDSM/MMA shadow (slot safe: barrier passed)
        int s2 = s + 2; if (s2 >= STAGES) s2 -= STAGES;
        if (kt + 2 < NKT) issue_stage(kt + 2, s2);
        CP_COMMIT();                      // uniform accounting

        // ks=0 MMA burst
        #pragma unroll
        for (int mf = 0; mf < 4; ++mf)
            #pragma unroll
            for (int nf = 0; nf < 4; ++nf)
                mma16816(acc[mf][nf], afr[mf],
                         bfr[nf >> 1][nf & 1], bfr[nf >> 1][(nf & 1) + 2]);

        // ks = 1..3
        #pragma unroll
        for (int ks = 1; ks < 4; ++ks) {
            load_frags(stA, stB, ks, afr, bfr);
            #pragma unroll
            for (int mf = 0; mf < 4; ++mf)
                #pragma unroll
                for (int nf = 0; nf < 4; ++nf)
                    mma16816(acc[mf][nf], afr[mf],
                             bfr[nf >> 1][nf & 1], bfr[nf >> 1][(nf & 1) + 2]);
        }
        if (++s == STAGES) s = 0;
    }

    // ---- epilogue: regs -> gmem (+bias), streaming stores ----
    float2 bv[4];
    #pragma unroll
    for (int nf = 0; nf < 4; ++nf)
        bv[nf] = *(const float2*)(bias + n0 + wn * 32 + nf * 8 + (lane & 3) * 2);

    #pragma unroll
    for (int mf = 0; mf < 4; ++mf) {
        const int r = m0 + wm * 64 + mf * 16 + (lane >> 2);
        #pragma unroll
        for (int nf = 0; nf < 4; ++nf) {
            const int c = n0 + wn * 32 + nf * 8 + (lane & 3) * 2;
            stcs2(out + (size_t)r * N_TOTAL + c,
                  acc[mf][nf][0] + bv[nf].x, acc[mf][nf][1] + bv[nf].y);
            stcs2(out + (size_t)(r + 8) * N_TOTAL + c,
                  acc[mf][nf][2] + bv[nf].x, acc[mf][nf][3] + bv[nf].y);
        }
    }
}

// ===================== host launch =====================
extern "C" void kernel_launch(void* const* d_in, const int* in_sizes, int n_in,
                              void* d_out, int out_size) {
    const float* x = nullptr;
    const float* w = nullptr;
    const float* bias = nullptr;
    for (int i = 0; i < n_in; ++i) {
        if (in_sizes[i] == M_TOTAL * K_TOTAL)      x = (const float*)d_in[i];
        else if (in_sizes[i] == N_TOTAL * K_TOTAL) w = (const float*)d_in[i];
        else if (in_sizes[i] == N_TOTAL)           bias = (const float*)d_in[i];
    }
    float* out = (float*)d_out;

    static bool attr_set = false;
    if (!attr_set) {
        cudaFuncSetAttribute(gemm_kernel,
                             cudaFuncAttributeMaxDynamicSharedMemorySize, SMEM_BYTES);
        attr_set = true;
    }

    // merged pack prepass
    {
        size_t chunks = TX_CHUNKS + TW_CHUNKS;
        pack_both_kernel<<<(unsigned)((chunks + 511) / 512), 512>>>(
            (const float4*)x, (const float4*)w);
    }

    // GEMM: each CTA = 3 tiles (one per group)
    gemm_kernel<<<(NTILES + GROUPS - 1) / GROUPS, GTHREADS, SMEM_BYTES>>>(out, bias);
}

// round 16
// speedup vs baseline: 1.0120x; 1.0120x over previous
#include <cuda_runtime.h>
#include <cuda_fp16.h>
#include <cstdint>

// ===================== problem constants =====================
#define M_TOTAL 8192
#define N_TOTAL 4096
#define K_TOTAL 4096
#define THRESH  0.1f

// ===================== GEMM tiling =====================
// One 384-thread CTA = THREE independent 4-warp pipelines ("groups").
// Each group: 128x64 output tile, THREE-stage ring, own named barrier.
// Warp tile 64x32. wait_group 1 keeps one stage in flight across the wait.
// (R14 configuration — measured optimum of this design space.)
#define BM 128
#define BN 64
#define BK 64            // halves per k-stage (128 bytes per row)
#define STAGES 3
#define GROUPS 3
#define GTHREADS 384
#define NKT (K_TOTAL / BK)                          // 64
#define NT  (N_TOTAL / BN)                          // 64 n-tiles
#define NTILES ((M_TOTAL / BM) * NT)                // 4096

#define A_REGION     (BM * BK * 2)                  // 16384
#define STAGE_BYTES  ((BM + BN) * BK * 2)           // 24576
#define GROUP_BYTES  (STAGES * STAGE_BYTES)         // 73728
#define SMEM_BYTES   (GROUPS * GROUP_BYTES)         // 221184 (<= 227KB cap)

// ===================== scratch (device globals, allocation-free) ==========
__device__ __half g_A[(size_t)M_TOTAL * K_TOTAL];   // 64 MB, x in fp16
__device__ __half g_B[(size_t)N_TOTAL * K_TOTAL];   // 32 MB, ternary(w) in fp16

// ===================== helpers =====================
static __device__ __forceinline__ uint32_t smem_u32(const void* p) {
    uint32_t a;
    asm("{ .reg .u64 t; cvta.to.shared.u64 t, %1; cvt.u32.u64 %0, t; }"
        : "=r"(a) : "l"(p));
    return a;
}

static __device__ __forceinline__ void cp16(uint32_t dst, const void* src) {
    asm volatile("cp.async.cg.shared.global [%0], [%1], 16;"
                 :: "r"(dst), "l"(src) : "memory");
}
#define CP_COMMIT() asm volatile("cp.async.commit_group;" ::: "memory")
#define CP_WAIT1()  asm volatile("cp.async.wait_group 1;"  ::: "memory")

// named barrier: independent sync domain per 4-warp group (128 threads)
static __device__ __forceinline__ void barg(int id) {
    asm volatile("bar.sync %0, %1;" :: "r"(id), "r"(128) : "memory");
}

static __device__ __forceinline__ void ldm_x4(uint32_t* r, uint32_t addr) {
    asm volatile("ldmatrix.sync.aligned.m8n8.x4.shared.b16 {%0,%1,%2,%3}, [%4];"
                 : "=r"(r[0]), "=r"(r[1]), "=r"(r[2]), "=r"(r[3]) : "r"(addr));
}

static __device__ __forceinline__ void mma16816(float* c, const uint32_t* a,
                                                uint32_t b0, uint32_t b1) {
    asm volatile(
        "mma.sync.aligned.m16n8k16.row.col.f32.f16.f16.f32 "
        "{%0,%1,%2,%3}, {%4,%5,%6,%7}, {%8,%9}, {%0,%1,%2,%3};"
        : "+f"(c[0]), "+f"(c[1]), "+f"(c[2]), "+f"(c[3])
        : "r"(a[0]), "r"(a[1]), "r"(a[2]), "r"(a[3]), "r"(b0), "r"(b1));
}

static __device__ __forceinline__ void stcs2(float* p, float x, float y) {
    asm volatile("st.global.cs.v2.f32 [%0], {%1, %2};" :: "l"(p), "f"(x), "f"(y) : "memory");
}

// ===================== merged pack kernel =====================
static __device__ __forceinline__ float tern(float v) {
    return (v > THRESH) ? 1.0f : ((v < -THRESH) ? -1.0f : 0.0f);
}

#define TX_CHUNKS ((size_t)M_TOTAL * K_TOTAL / 8)   // 4,194,304
#define TW_CHUNKS ((size_t)N_TOTAL * K_TOTAL / 8)   // 2,097,152

__global__ void __launch_bounds__(512) pack_both_kernel(const float4* __restrict__ x,
                                                        const float4* __restrict__ w) {
    size_t i = (size_t)blockIdx.x * blockDim.x + threadIdx.x;
    if (i < TX_CHUNKS) {
        float4 v0 = __ldcs(&x[i * 2]);       // streaming: keep L2 for g_A/g_B
        float4 v1 = __ldcs(&x[i * 2 + 1]);
        __half2 h0 = __floats2half2_rn(v0.x, v0.y);
        __half2 h1 = __floats2half2_rn(v0.z, v0.w);
        __half2 h2 = __floats2half2_rn(v1.x, v1.y);
        __half2 h3 = __floats2half2_rn(v1.z, v1.w);
        uint4 u;
        u.x = *(uint32_t*)&h0; u.y = *(uint32_t*)&h1;
        u.z = *(uint32_t*)&h2; u.w = *(uint32_t*)&h3;
        *(uint4*)(&g_A[i * 8]) = u;
    } else {
        size_t j = i - TX_CHUNKS;
        if (j >= TW_CHUNKS) return;
        float4 v0 = __ldcs(&w[j * 2]);
        float4 v1 = __ldcs(&w[j * 2 + 1]);
        __half2 h0 = __floats2half2_rn(tern(v0.x), tern(v0.y));
        __half2 h1 = __floats2half2_rn(tern(v0.z), tern(v0.w));
        __half2 h2 = __floats2half2_rn(tern(v1.x), tern(v1.y));
        __half2 h3 = __floats2half2_rn(tern(v1.z), tern(v1.w));
        uint4 u;
        u.x = *(uint32_t*)&h0; u.y = *(uint32_t*)&h1;
        u.z = *(uint32_t*)&h2; u.w = *(uint32_t*)&h3;
        *(uint4*)(&g_B[j * 8]) = u;
    }
}

// ===================== GEMM kernel =====================
// A fp16 [M][K] row-major, B fp16 [N][K] row-major (TN gemm).
// SMEM rows 128B; swizzle: 16B-chunk c -> c ^ (row & 7).
// Group g handles tile (blockIdx.x*3 + g); 3-stage ring:
//   kt: wait_group 1 (slot kt landed; kt+1 may fly) -> barg ->
//       issue kt+2 -> compute kt.
__global__ void __launch_bounds__(GTHREADS, 1)
gemm_kernel(float* __restrict__ out, const float* __restrict__ bias) {
    extern __shared__ __half smem[];
    const uint32_t sbase = smem_u32(smem);

    const int tid   = threadIdx.x;
    const int g     = tid >> 7;          // group 0..2
    const int lane  = tid & 31;
    const int wid_g = (tid >> 5) & 3;    // warp within group
    const int wm    = wid_g & 1;         // 0..1 : M (64-row slab)
    const int wn    = wid_g >> 1;        // 0..1 : N (32-col slab)
    const int barid = g + 1;

    const int t  = blockIdx.x * GROUPS + g;   // this group's tile
    if (t >= NTILES) return;                  // safe: barriers are group-local
    const int m0 = (t >> 6) * BM;             // NT = 64 n-tiles
    const int n0 = (t & 63) * BN;

    const __half* gA = g_A + (size_t)m0 * K_TOTAL;
    const __half* gB = g_B + (size_t)n0 * K_TOTAL;

    const uint32_t gbase = sbase + g * GROUP_BYTES;

    const int tg    = tid & 127;
    const int ldrow = tg >> 3;           // 0..15
    const int ldcol = tg & 7;            // 16B chunk 0..7
    const uint32_t ldsw = (uint32_t)((ldcol ^ (ldrow & 7)) << 4);

    // ---- async stage loader: A 128 rows + B 64 rows, 128B each, 128 thr ----
    auto issue_stage = [&](int kt, int s) {
        const uint32_t stA = gbase + s * STAGE_BYTES;
        const uint32_t stB = stA + A_REGION;
        const int kofs = kt * BK + ldcol * 8;
        #pragma unroll
        for (int i = 0; i < 8; ++i) {
            const int row = ldrow + i * 16;
            cp16(stA + row * 128 + ldsw, gA + (size_t)row * K_TOTAL + kofs);
        }
        #pragma unroll
        for (int i = 0; i < 4; ++i) {
            const int row = ldrow + i * 16;
            cp16(stB + row * 128 + ldsw, gB + (size_t)row * K_TOTAL + kofs);
        }
    };

    // prologue: stages 0,1
    issue_stage(0, 0); CP_COMMIT();
    issue_stage(1, 1); CP_COMMIT();

    float acc[4][4][4];
    #pragma unroll
    for (int i = 0; i < 4; ++i)
        #pragma unroll
        for (int j = 0; j < 4; ++j)
            #pragma unroll
            for (int e = 0; e < 4; ++e) acc[i][j][e] = 0.0f;

    int s = 0;                            // ring slot of kt
    #pragma unroll 1
    for (int kt = 0; kt < NKT; ++kt) {
        CP_WAIT1();                       // slot kt landed; kt+1 may still fly
        barg(barid);                      // group-wide publish + reuse safety

        int s2 = s + 2; if (s2 >= STAGES) s2 -= STAGES;
        if (kt + 2 < NKT) issue_stage(kt + 2, s2);
        CP_COMMIT();                      // uniform accounting

        const uint32_t stA = gbase + s * STAGE_BYTES;
        const uint32_t stB = stA + A_REGION;

        #pragma unroll
        for (int ks = 0; ks < 4; ++ks) {           // 4 x k16 per stage
            const int chunk = 2 * ks + (lane >> 4);
            uint32_t afr[4][4];
            #pragma unroll
            for (int mf = 0; mf < 4; ++mf) {
                const int row = wm * 64 + mf * 16 + (lane & 15);
                ldm_x4(afr[mf], stA + row * 128 + ((chunk ^ (row & 7)) << 4));
            }
            uint32_t bfr[2][4];
            #pragma unroll
            for (int nh = 0; nh < 2; ++nh) {
                const int row = wn * 32 + nh * 16 + (lane & 15);
                ldm_x4(bfr[nh], stB + row * 128 + ((chunk ^ (row & 7)) << 4));
            }
            #pragma unroll
            for (int mf = 0; mf < 4; ++mf) {
                #pragma unroll
                for (int nf = 0; nf < 4; ++nf) {
                    const uint32_t b0 = bfr[nf >> 1][nf & 1];
                    const uint32_t b1 = bfr[nf >> 1][(nf & 1) + 2];
                    mma16816(acc[mf][nf], afr[mf], b0, b1);
                }
            }
        }
        if (++s == STAGES) s = 0;
    }

    // ---- epilogue: regs -> gmem (+bias), streaming stores ----
    // bias depends only on nf: hoist the 4 float2 loads out of the mf loop
    float2 bv[4];
    #pragma unroll
    for (int nf = 0; nf < 4; ++nf)
        bv[nf] = *(const float2*)(bias + n0 + wn * 32 + nf * 8 + (lane & 3) * 2);

    #pragma unroll
    for (int mf = 0; mf < 4; ++mf) {
        const int r = m0 + wm * 64 + mf * 16 + (lane >> 2);
        #pragma unroll
        for (int nf = 0; nf < 4; ++nf) {
            const int c = n0 + wn * 32 + nf * 8 + (lane & 3) * 2;
            stcs2(out + (size_t)r * N_TOTAL + c,
                  acc[mf][nf][0] + bv[nf].x, acc[mf][nf][1] + bv[nf].y);
            stcs2(out + (size_t)(r + 8) * N_TOTAL + c,
                  acc[mf][nf][2] + bv[nf].x, acc[mf][nf][3] + bv[nf].y);
        }
    }
}

// ===================== host launch =====================
extern "C" void kernel_launch(void* const* d_in, const int* in_sizes, int n_in,
                              void* d_out, int out_size) {
    const float* x = nullptr;
    const float* w = nullptr;
    const float* bias = nullptr;
    for (int i = 0; i < n_in; ++i) {
        if (in_sizes[i] == M_TOTAL * K_TOTAL)      x = (const float*)d_in[i];
        else if (in_sizes[i] == N_TOTAL * K_TOTAL) w = (const float*)d_in[i];
        else if (in_sizes[i] == N_TOTAL)           bias = (const float*)d_in[i];
    }
    float* out = (float*)d_out;

    static bool attr_set = false;
    if (!attr_set) {
        cudaFuncSetAttribute(gemm_kernel,
                             cudaFuncAttributeMaxDynamicSharedMemorySize, SMEM_BYTES);
        attr_set = true;
    }

    // merged pack prepass
    {
        size_t chunks = TX_CHUNKS + TW_CHUNKS;
        pack_both_kernel<<<(unsigned)((chunks + 511) / 512), 512>>>(
            (const float4*)x, (const float4*)w);
    }

    // GEMM: each CTA = 3 tiles (one per group)
    gemm_kernel<<<(NTILES + GROUPS - 1) / GROUPS, GTHREADS, SMEM_BYTES>>>(out, bias);
}

// round 17
// speedup vs baseline: 1.0297x; 1.0175x over previous
#include <cuda_runtime.h>
#include <cuda_fp16.h>
#include <cstdint>

// ===================== problem constants =====================
#define M_TOTAL 8192
#define N_TOTAL 4096
#define K_TOTAL 4096
#define THRESH  0.1f

// ===================== GEMM tiling =====================
// One 384-thread CTA = THREE independent 4-warp pipelines ("groups").
// Each group: 128x64 output tile, THREE-stage ring, own named barrier.
// Warp tile 64x32. wait_group 1 keeps one stage in flight across the wait.
// kt loop unrolled by the ring period (3): stage slot is a compile-time
// constant in each body -> slot arithmetic and branches fold away.
#define BM 128
#define BN 64
#define BK 64            // halves per k-stage (128 bytes per row)
#define STAGES 3
#define GROUPS 3
#define GTHREADS 384
#define NKT (K_TOTAL / BK)                          // 64
#define NT  (N_TOTAL / BN)                          // 64 n-tiles
#define NTILES ((M_TOTAL / BM) * NT)                // 4096

#define A_REGION     (BM * BK * 2)                  // 16384
#define STAGE_BYTES  ((BM + BN) * BK * 2)           // 24576
#define GROUP_BYTES  (STAGES * STAGE_BYTES)         // 73728
#define SMEM_BYTES   (GROUPS * GROUP_BYTES)         // 221184 (<= 227KB cap)

// ===================== scratch (device globals, allocation-free) ==========
__device__ __half g_A[(size_t)M_TOTAL * K_TOTAL];   // 64 MB, x in fp16
__device__ __half g_B[(size_t)N_TOTAL * K_TOTAL];   // 32 MB, ternary(w) in fp16

// ===================== helpers =====================
static __device__ __forceinline__ uint32_t smem_u32(const void* p) {
    uint32_t a;
    asm("{ .reg .u64 t; cvta.to.shared.u64 t, %1; cvt.u32.u64 %0, t; }"
        : "=r"(a) : "l"(p));
    return a;
}

static __device__ __forceinline__ void cp16(uint32_t dst, const void* src) {
    asm volatile("cp.async.cg.shared.global [%0], [%1], 16;"
                 :: "r"(dst), "l"(src) : "memory");
}
#define CP_COMMIT() asm volatile("cp.async.commit_group;" ::: "memory")
#define CP_WAIT1()  asm volatile("cp.async.wait_group 1;"  ::: "memory")

// named barrier: independent sync domain per 4-warp group (128 threads)
static __device__ __forceinline__ void barg(int id) {
    asm volatile("bar.sync %0, %1;" :: "r"(id), "r"(128) : "memory");
}

static __device__ __forceinline__ void ldm_x4(uint32_t* r, uint32_t addr) {
    asm volatile("ldmatrix.sync.aligned.m8n8.x4.shared.b16 {%0,%1,%2,%3}, [%4];"
                 : "=r"(r[0]), "=r"(r[1]), "=r"(r[2]), "=r"(r[3]) : "r"(addr));
}

static __device__ __forceinline__ void mma16816(float* c, const uint32_t* a,
                                                uint32_t b0, uint32_t b1) {
    asm volatile(
        "mma.sync.aligned.m16n8k16.row.col.f32.f16.f16.f32 "
        "{%0,%1,%2,%3}, {%4,%5,%6,%7}, {%8,%9}, {%0,%1,%2,%3};"
        : "+f"(c[0]), "+f"(c[1]), "+f"(c[2]), "+f"(c[3])
        : "r"(a[0]), "r"(a[1]), "r"(a[2]), "r"(a[3]), "r"(b0), "r"(b1));
}

static __device__ __forceinline__ void stcs2(float* p, float x, float y) {
    asm volatile("st.global.cs.v2.f32 [%0], {%1, %2};" :: "l"(p), "f"(x), "f"(y) : "memory");
}

// ===================== merged pack kernel =====================
static __device__ __forceinline__ float tern(float v) {
    return (v > THRESH) ? 1.0f : ((v < -THRESH) ? -1.0f : 0.0f);
}

#define TX_CHUNKS ((size_t)M_TOTAL * K_TOTAL / 8)   // 4,194,304
#define TW_CHUNKS ((size_t)N_TOTAL * K_TOTAL / 8)   // 2,097,152

__global__ void __launch_bounds__(512) pack_both_kernel(const float4* __restrict__ x,
                                                        const float4* __restrict__ w) {
    size_t i = (size_t)blockIdx.x * blockDim.x + threadIdx.x;
    if (i < TX_CHUNKS) {
        float4 v0 = __ldcs(&x[i * 2]);       // streaming: keep L2 for g_A/g_B
        float4 v1 = __ldcs(&x[i * 2 + 1]);
        __half2 h0 = __floats2half2_rn(v0.x, v0.y);
        __half2 h1 = __floats2half2_rn(v0.z, v0.w);
        __half2 h2 = __floats2half2_rn(v1.x, v1.y);
        __half2 h3 = __floats2half2_rn(v1.z, v1.w);
        uint4 u;
        u.x = *(uint32_t*)&h0; u.y = *(uint32_t*)&h1;
        u.z = *(uint32_t*)&h2; u.w = *(uint32_t*)&h3;
        *(uint4*)(&g_A[i * 8]) = u;
    } else {
        size_t j = i - TX_CHUNKS;
        if (j >= TW_CHUNKS) return;
        float4 v0 = __ldcs(&w[j * 2]);
        float4 v1 = __ldcs(&w[j * 2 + 1]);
        __half2 h0 = __floats2half2_rn(tern(v0.x), tern(v0.y));
        __half2 h1 = __floats2half2_rn(tern(v0.z), tern(v0.w));
        __half2 h2 = __floats2half2_rn(tern(v1.x), tern(v1.y));
        __half2 h3 = __floats2half2_rn(tern(v1.z), tern(v1.w));
        uint4 u;
        u.x = *(uint32_t*)&h0; u.y = *(uint32_t*)&h1;
        u.z = *(uint32_t*)&h2; u.w = *(uint32_t*)&h3;
        *(uint4*)(&g_B[j * 8]) = u;
    }
}

// ===================== GEMM kernel =====================
// A fp16 [M][K] row-major, B fp16 [N][K] row-major (TN gemm).
// SMEM rows 128B; swizzle: 16B-chunk c -> c ^ (row & 7).
// Group g handles tile (blockIdx.x*3 + g). Ring slot of kt = kt % 3.
__global__ void __launch_bounds__(GTHREADS, 1)
gemm_kernel(float* __restrict__ out, const float* __restrict__ bias) {
    extern __shared__ __half smem[];
    const uint32_t sbase = smem_u32(smem);

    const int tid   = threadIdx.x;
    const int g     = tid >> 7;          // group 0..2
    const int lane  = tid & 31;
    const int wid_g = (tid >> 5) & 3;    // warp within group
    const int wm    = wid_g & 1;         // 0..1 : M (64-row slab)
    const int wn    = wid_g >> 1;        // 0..1 : N (32-col slab)
    const int barid = g + 1;

    const int t  = blockIdx.x * GROUPS + g;   // this group's tile
    if (t >= NTILES) return;                  // safe: barriers are group-local
    const int m0 = (t >> 6) * BM;             // NT = 64 n-tiles
    const int n0 = (t & 63) * BN;

    const __half* gA = g_A + (size_t)m0 * K_TOTAL;
    const __half* gB = g_B + (size_t)n0 * K_TOTAL;

    const uint32_t gbase = sbase + g * GROUP_BYTES;

    const int tg    = tid & 127;
    const int ldrow = tg >> 3;           // 0..15
    const int ldcol = tg & 7;            // 16B chunk 0..7
    const uint32_t ldsw = (uint32_t)((ldcol ^ (ldrow & 7)) << 4);

    // ---- async stage loader: A 128 rows + B 64 rows, 128B each, 128 thr ----
    auto issue_stage = [&](int kt, int s) {
        const uint32_t stA = gbase + s * STAGE_BYTES;
        const uint32_t stB = stA + A_REGION;
        const int kofs = kt * BK + ldcol * 8;
        #pragma unroll
        for (int i = 0; i < 8; ++i) {
            const int row = ldrow + i * 16;
            cp16(stA + row * 128 + ldsw, gA + (size_t)row * K_TOTAL + kofs);
        }
        #pragma unroll
        for (int i = 0; i < 4; ++i) {
            const int row = ldrow + i * 16;
            cp16(stB + row * 128 + ldsw, gB + (size_t)row * K_TOTAL + kofs);
        }
    };

    // prologue: stages 0,1
    issue_stage(0, 0); CP_COMMIT();
    issue_stage(1, 1); CP_COMMIT();

    float acc[4][4][4];
    #pragma unroll
    for (int i = 0; i < 4; ++i)
        #pragma unroll
        for (int j = 0; j < 4; ++j)
            #pragma unroll
            for (int e = 0; e < 4; ++e) acc[i][j][e] = 0.0f;

    // one kt body; S is a compile-time slot constant, DO_PF a literal
#define KT_BODY(KT, S, DO_PF) do {                                            \
        CP_WAIT1();                       /* slot (KT) landed */               \
        barg(barid);                      /* publish + reuse safety */         \
        if (DO_PF) issue_stage((KT) + 2, ((S) + 2) % STAGES);                  \
        CP_COMMIT();                      /* uniform accounting */             \
        const uint32_t stA = gbase + (S) * STAGE_BYTES;                        \
        const uint32_t stB = stA + A_REGION;                                   \
        _Pragma("unroll")                                                      \
        for (int ks = 0; ks < 4; ++ks) {                                       \
            const int chunk = 2 * ks + (lane >> 4);                            \
            uint32_t afr[4][4];                                                \
            _Pragma("unroll")                                                  \
            for (int mf = 0; mf < 4; ++mf) {                                   \
                const int row = wm * 64 + mf * 16 + (lane & 15);               \
                ldm_x4(afr[mf], stA + row * 128 + ((chunk ^ (row & 7)) << 4)); \
            }                                                                  \
            uint32_t bfr[2][4];                                                \
            _Pragma("unroll")                                                  \
            for (int nh = 0; nh < 2; ++nh) {                                   \
                const int row = wn * 32 + nh * 16 + (lane & 15);               \
                ldm_x4(bfr[nh], stB + row * 128 + ((chunk ^ (row & 7)) << 4)); \
            }                                                                  \
            _Pragma("unroll")                                                  \
            for (int mf = 0; mf < 4; ++mf) {                                   \
                _Pragma("unroll")                                              \
                for (int nf = 0; nf < 4; ++nf) {                               \
                    const uint32_t b0 = bfr[nf >> 1][nf & 1];                  \
                    const uint32_t b1 = bfr[nf >> 1][(nf & 1) + 2];            \
                    mma16816(acc[mf][nf], afr[mf], b0, b1);                    \
                }                                                              \
            }                                                                  \
        }                                                                      \
    } while (0)

    // main loop: kt = 0..59 in ring-period triples (slots 0,1,2 literal)
    #pragma unroll 1
    for (int kt0 = 0; kt0 < 60; kt0 += 3) {
        KT_BODY(kt0 + 0, 0, true);
        KT_BODY(kt0 + 1, 1, true);
        KT_BODY(kt0 + 2, 2, true);
    }
    // tail: kt = 60..63 (prefetch exact: 62 -> slot2, 63 -> slot0, then none)
    KT_BODY(60, 0, true);
    KT_BODY(61, 1, true);
    KT_BODY(62, 2, false);
    KT_BODY(63, 0, false);
#undef KT_BODY

    // ---- epilogue: regs -> gmem (+bias), streaming stores ----
    float2 bv[4];
    #pragma unroll
    for (int nf = 0; nf < 4; ++nf)
        bv[nf] = *(const float2*)(bias + n0 + wn * 32 + nf * 8 + (lane & 3) * 2);

    #pragma unroll
    for (int mf = 0; mf < 4; ++mf) {
        const int r = m0 + wm * 64 + mf * 16 + (lane >> 2);
        #pragma unroll
        for (int nf = 0; nf < 4; ++nf) {
            const int c = n0 + wn * 32 + nf * 8 + (lane & 3) * 2;
            stcs2(out + (size_t)r * N_TOTAL + c,
                  acc[mf][nf][0] + bv[nf].x, acc[mf][nf][1] + bv[nf].y);
            stcs2(out + (size_t)(r + 8) * N_TOTAL + c,
                  acc[mf][nf][2] + bv[nf].x, acc[mf][nf][3] + bv[nf].y);
        }
    }
}

// ===================== host launch =====================
extern "C" void kernel_launch(void* const* d_in, const int* in_sizes, int n_in,
                              void* d_out, int out_size) {
    const float* x = nullptr;
    const float* w = nullptr;
    const float* bias = nullptr;
    for (int i = 0; i < n_in; ++i) {
        if (in_sizes[i] == M_TOTAL * K_TOTAL)      x = (const float*)d_in[i];
        else if (in_sizes[i] == N_TOTAL * K_TOTAL) w = (const float*)d_in[i];
        else if (in_sizes[i] == N_TOTAL)           bias = (const float*)d_in[i];
    }
    float* out = (float*)d_out;

    static bool attr_set = false;
    if (!attr_set) {
        cudaFuncSetAttribute(gemm_kernel,
                             cudaFuncAttributeMaxDynamicSharedMemorySize, SMEM_BYTES);
        attr_set = true;
    }

    // merged pack prepass
    {
        size_t chunks = TX_CHUNKS + TW_CHUNKS;
        pack_both_kernel<<<(unsigned)((chunks + 511) / 512), 512>>>(
            (const float4*)x, (const float4*)w);
    }

    // GEMM: each CTA = 3 tiles (one per group)
    gemm_kernel<<<(NTILES + GROUPS - 1) / GROUPS, GTHREADS, SMEM_BYTES>>>(out, bias);
}